// round 9
// baseline (speedup 1.0000x reference)
#include <cuda_runtime.h>
#include <cstdint>

#define E_    32
#define KK    4
#define H_    1024
#define F_    1024
#define T_    1024
#define TWO_F 2048
#define NSLOT (T_*KK)

// ---------------- scratch (device globals; no allocation) ----------------
__device__ float g_t[T_*H_];
__device__ float g_topk_w[T_*KK];
__device__ int   g_topk_i[T_*KK];
__device__ int   g_cnt[E_];
__device__ int   g_off[E_];
__device__ int   g_tok[NSLOT];
__device__ float g_sw[NSLOT];
__device__ int   g_tslot[T_*KK];
__device__ float g_act[(size_t)NSLOT*F_];
__device__ float g_comb[(size_t)NSLOT*H_];

// ---------------- helpers ----------------
__device__ __forceinline__ uint32_t smem_u32(const void* p) {
    uint32_t a;
    asm("{ .reg .u64 t; cvta.to.shared.u64 t, %1; cvt.u32.u64 %0, t; }" : "=r"(a) : "l"(p));
    return a;
}

#define CPA16(dst, src, sz) \
    asm volatile("cp.async.ca.shared.global [%0], [%1], 16, %2;" \
        :: "r"(dst), "l"(src), "r"(sz))

#define CPA_COMMIT() asm volatile("cp.async.commit_group;")
#define CPA_WAIT2()  asm volatile("cp.async.wait_group 2;")
#define CPA_WAIT0()  asm volatile("cp.async.wait_group 0;")

#define LDMX4(r, addr) \
    asm volatile("ldmatrix.sync.aligned.m8n8.x4.shared.b16 {%0,%1,%2,%3}, [%4];" \
        : "=r"((r)[0]), "=r"((r)[1]), "=r"((r)[2]), "=r"((r)[3]) : "r"(addr))

#define MMA8(d, a, b0, b1) \
    asm volatile("mma.sync.aligned.m16n8k8.row.col.f32.tf32.tf32.f32 " \
        "{%0,%1,%2,%3}, {%4,%5,%6,%7}, {%8,%9}, {%0,%1,%2,%3};" \
        : "+f"((d)[0]), "+f"((d)[1]), "+f"((d)[2]), "+f"((d)[3]) \
        : "r"((a)[0]), "r"((a)[1]), "r"((a)[2]), "r"((a)[3]), "r"(b0), "r"(b1))

// dynamic smem: [0,512) rowtok; 4 stages: A (128x128B=16KB) + B (16KB) each
#define SM_STAGE0  1024
#define STAGE_B    32768
#define SMEM_MLP   (SM_STAGE0 + 4 * STAGE_B)   // 132096 B -> 1 CTA/SM (512 thr)

// ---------------- kernel 1: fused rmsnorm + gate + top-4 softmax ----------------
__global__ void __launch_bounds__(256) k_norm_gate(
    const float* __restrict__ x, const float* __restrict__ scale,
    const float* __restrict__ gw, const float* __restrict__ gb) {
    __shared__ float ts[H_];
    __shared__ float red[8];
    __shared__ float lg[E_];
    int t = blockIdx.x;
    const float* xr = x + (size_t)t * H_;
    float s = 0.f;
    float xv[4];
    #pragma unroll
    for (int i = 0; i < 4; i++) { xv[i] = xr[threadIdx.x + i * 256]; s += xv[i] * xv[i]; }
    for (int o = 16; o; o >>= 1) s += __shfl_down_sync(0xffffffffu, s, o);
    if ((threadIdx.x & 31) == 0) red[threadIdx.x >> 5] = s;
    __syncthreads();
    if (threadIdx.x < 8) {
        s = red[threadIdx.x];
        for (int o = 4; o; o >>= 1) s += __shfl_down_sync(0xffu, s, o);
        if (threadIdx.x == 0) red[0] = rsqrtf(s / (float)H_ + 1e-5f);
    }
    __syncthreads();
    float r = red[0];
    #pragma unroll
    for (int i = 0; i < 4; i++) {
        int h = threadIdx.x + i * 256;
        float v = xv[i] * r * scale[h];
        ts[h] = v;
        g_t[(size_t)t * H_ + h] = v;
    }
    __syncthreads();
    int e = threadIdx.x >> 3, j = threadIdx.x & 7;
    const float* wr = gw + (size_t)e * H_;
    float acc = 0.f;
    for (int h = j * 4; h < H_; h += 32)
        acc += ts[h]*wr[h] + ts[h+1]*wr[h+1] + ts[h+2]*wr[h+2] + ts[h+3]*wr[h+3];
    for (int o = 4; o; o >>= 1) acc += __shfl_down_sync(0xffffffffu, acc, o);
    if (j == 0) lg[e] = acc + gb[e];
    __syncthreads();
    if (threadIdx.x == 0) {
        float v[E_];
        #pragma unroll
        for (int i = 0; i < E_; i++) v[i] = lg[i];
        float tv[KK]; int ti[KK];
        for (int k = 0; k < KK; k++) {
            float best = -1e30f; int bi = 0;
            for (int i = 0; i < E_; i++) if (v[i] > best) { best = v[i]; bi = i; }
            tv[k] = best; ti[k] = bi; v[bi] = -1e30f;
        }
        float m = tv[0], den = 0.f, ex[KK];
        for (int k = 0; k < KK; k++) { ex[k] = expf(tv[k] - m); den += ex[k]; }
        for (int k = 0; k < KK; k++) {
            g_topk_w[t*KK + k] = ex[k] / den;
            g_topk_i[t*KK + k] = ti[k];
        }
    }
}

// ---------------- kernel 2: parallel deterministic grouping ----------------
__global__ void __launch_bounds__(1024) k_build() {
    __shared__ uint32_t wmask[32][E_];
    __shared__ int scanwe[32][E_];
    __shared__ int cnt_s[E_], off_s[E_];
    int t = threadIdx.x, w = t >> 5, lane = t & 31;

    ((uint32_t*)wmask)[t] = 0u;
    __syncthreads();

    int es[KK]; float ws[KK];
    #pragma unroll
    for (int j = 0; j < KK; j++) {
        es[j] = g_topk_i[t * KK + j];
        ws[j] = g_topk_w[t * KK + j];
        atomicOr(&wmask[w][es[j]], 1u << lane);
    }
    __syncthreads();

    if (t < E_) {
        int run = 0;
        #pragma unroll
        for (int ww = 0; ww < 32; ww++) {
            scanwe[ww][t] = run;
            run += __popc(wmask[ww][t]);
        }
        cnt_s[t] = run;
        g_cnt[t] = run;
    }
    __syncthreads();
    if (t == 0) {
        int r = 0;
        #pragma unroll
        for (int i = 0; i < E_; i++) { off_s[i] = r; g_off[i] = r; r += cnt_s[i]; }
    }
    __syncthreads();

    uint32_t ltmask = (1u << lane) - 1u;
    #pragma unroll
    for (int j = 0; j < KK; j++) {
        int e = es[j];
        int p = off_s[e] + scanwe[w][e] + __popc(wmask[w][e] & ltmask);
        g_tok[p] = t;
        g_sw[p] = ws[j];
        g_tslot[t * KK + j] = p;
    }
}

// =====================================================================
// grouped GEMM: BM=128, BN=128, BK=32, 512 threads (16 warps as 4Mx4N,
// warp tile 32x32), 4-stage cp.async pipeline (3-tile lead > DRAM lat),
// ldmatrix.x4.b16 on XOR-swizzled K-major tiles, reg->gmem epilogue.
// =====================================================================

__device__ __forceinline__ float swiglu(float glu, float lin) {
    glu = fminf(glu, 7.0f);
    lin = fminf(fmaxf(lin, -7.0f), 7.0f);
    float sig = 1.f / (1.f + __expf(-1.702f * glu));
    return glu * sig * (lin + 1.f);
}

__global__ void __launch_bounds__(512, 1)
k_mlp1(const float* __restrict__ w1, const float* __restrict__ b1) {
    extern __shared__ char smem[];
    int e = blockIdx.z, mtile = blockIdx.y, ntile = blockIdx.x;
    int cnt = g_cnt[e];
    if (mtile * 128 >= cnt) return;
    int off = g_off[e];
    int tid = threadIdx.x, wid = tid >> 5, lane = tid & 31;
    int wm = wid & 3, wn = wid >> 2;
    int grp = lane >> 3, rin = lane & 7;
    uint32_t sb = smem_u32(smem);

    int* rowtok = (int*)smem;
    if (tid < 128) {
        int m = mtile * 128 + tid;
        rowtok[tid] = (m < cnt) ? g_tok[off + m] : -1;
    }
    __syncthreads();

    const float* Bb = w1 + ((size_t)e * TWO_F + (size_t)ntile * 128) * H_;

    int frow = tid >> 3, fc = tid & 7;                 // 64 rows per i-step
    uint32_t fswz = (uint32_t)((fc ^ (frow & 7)) * 16);

    auto issue = [&](int kt) {
        int s = kt & 3;
        int k0 = kt * 32;
        uint32_t Ab = sb + SM_STAGE0 + s * STAGE_B;
        uint32_t Bbuf = Ab + 16384;
        #pragma unroll
        for (int i = 0; i < 2; i++) {
            int row = frow + i * 64;
            int tok = rowtok[row];
            const float* src = g_t + (size_t)(tok < 0 ? 0 : tok) * H_ + k0 + fc * 4;
            int sz = (tok >= 0) ? 16 : 0;
            CPA16(Ab + row * 128 + fswz, src, sz);
        }
        #pragma unroll
        for (int i = 0; i < 2; i++) {
            int row = frow + i * 64;
            const float* src = Bb + (size_t)row * H_ + k0 + fc * 4;
            CPA16(Bbuf + row * 128 + fswz, src, 16);
        }
        CPA_COMMIT();
    };

    float acc[2][4][4];
    #pragma unroll
    for (int mi = 0; mi < 2; mi++)
        #pragma unroll
        for (int ni = 0; ni < 4; ni++)
            #pragma unroll
            for (int q = 0; q < 4; q++) acc[mi][ni][q] = 0.f;

    issue(0); issue(1); issue(2);

    uint32_t aOff = (uint32_t)((wm * 32 + (grp & 1) * 8 + rin) * 128);
    uint32_t bOff = (uint32_t)((wn * 32 + (grp >> 1) * 8 + rin) * 128);
    int caH = grp >> 1, cbH = grp & 1;

    for (int kt = 0; kt < 32; kt++) {
        if (kt < 30) { CPA_WAIT2(); } else { CPA_WAIT0(); }
        __syncthreads();
        if (kt + 3 < 32) issue(kt + 3);

        uint32_t Ab = sb + SM_STAGE0 + (kt & 3) * STAGE_B;
        uint32_t Bbuf = Ab + 16384;
        uint32_t aBase = Ab + aOff;
        uint32_t bBase = Bbuf + bOff;

        #pragma unroll
        for (int ks = 0; ks < 4; ks++) {
            uint32_t a[2][4], b[2][4];
            uint32_t ca = (uint32_t)(((2 * ks + caH) ^ rin) * 16);
            uint32_t cb = (uint32_t)(((2 * ks + cbH) ^ rin) * 16);
            LDMX4(a[0], aBase + ca);
            LDMX4(a[1], aBase + 2048 + ca);
            LDMX4(b[0], bBase + cb);
            LDMX4(b[1], bBase + 2048 + cb);
            #pragma unroll
            for (int mi = 0; mi < 2; mi++)
                #pragma unroll
                for (int j = 0; j < 2; j++) {
                    MMA8(acc[mi][2*j],     a[mi], b[j][0], b[j][1]);
                    MMA8(acc[mi][2*j + 1], a[mi], b[j][2], b[j][3]);
                }
        }
    }

    // fused epilogue: bias + interleaved swiglu, regs -> g_act
    int nv = min(128, cnt - mtile * 128);
    int q = lane & 3, rr = lane >> 2;
    const float* b1p = b1 + (size_t)e * TWO_F + ntile * 128 + wn * 32;
    int acol0 = ntile * 64 + wn * 16;
    int mrowbase = off + mtile * 128;
    #pragma unroll
    for (int mi = 0; mi < 2; mi++) {
        int r1 = wm * 32 + mi * 16 + rr;
        #pragma unroll
        for (int ni = 0; ni < 4; ni++) {
            float be = __ldg(b1p + ni * 8 + 2 * q);
            float bo = __ldg(b1p + ni * 8 + 2 * q + 1);
            int ac = acol0 + ni * 4 + q;
            if (r1 < nv)
                g_act[(size_t)(mrowbase + r1) * F_ + ac] =
                    swiglu(acc[mi][ni][0] + be, acc[mi][ni][1] + bo);
            if (r1 + 8 < nv)
                g_act[(size_t)(mrowbase + r1 + 8) * F_ + ac] =
                    swiglu(acc[mi][ni][2] + be, acc[mi][ni][3] + bo);
        }
    }
}

__global__ void __launch_bounds__(512, 1)
k_mlp2(const float* __restrict__ w2, const float* __restrict__ b2) {
    extern __shared__ char smem[];
    int e = blockIdx.z, mtile = blockIdx.y, ntile = blockIdx.x;
    int cnt = g_cnt[e];
    if (mtile * 128 >= cnt) return;
    int off = g_off[e];
    int tid = threadIdx.x, wid = tid >> 5, lane = tid & 31;
    int wm = wid & 3, wn = wid >> 2;
    int grp = lane >> 3, rin = lane & 7;
    uint32_t sb = smem_u32(smem);

    const float* Bb = w2 + ((size_t)e * H_ + (size_t)ntile * 128) * F_;

    int frow = tid >> 3, fc = tid & 7;
    uint32_t fswz = (uint32_t)((fc ^ (frow & 7)) * 16);

    auto issue = [&](int kt) {
        int s = kt & 3;
        int k0 = kt * 32;
        uint32_t Ab = sb + SM_STAGE0 + s * STAGE_B;
        uint32_t Bbuf = Ab + 16384;
        #pragma unroll
        for (int i = 0; i < 2; i++) {
            int row = frow + i * 64;
            int m = mtile * 128 + row;
            int mc = min(m, cnt - 1);
            const float* src = g_act + (size_t)(off + mc) * F_ + k0 + fc * 4;
            int sz = (m < cnt) ? 16 : 0;
            CPA16(Ab + row * 128 + fswz, src, sz);
        }
        #pragma unroll
        for (int i = 0; i < 2; i++) {
            int row = frow + i * 64;
            const float* src = Bb + (size_t)row * F_ + k0 + fc * 4;
            CPA16(Bbuf + row * 128 + fswz, src, 16);
        }
        CPA_COMMIT();
    };

    float acc[2][4][4];
    #pragma unroll
    for (int mi = 0; mi < 2; mi++)
        #pragma unroll
        for (int ni = 0; ni < 4; ni++)
            #pragma unroll
            for (int q = 0; q < 4; q++) acc[mi][ni][q] = 0.f;

    issue(0); issue(1); issue(2);

    uint32_t aOff = (uint32_t)((wm * 32 + (grp & 1) * 8 + rin) * 128);
    uint32_t bOff = (uint32_t)((wn * 32 + (grp >> 1) * 8 + rin) * 128);
    int caH = grp >> 1, cbH = grp & 1;

    for (int kt = 0; kt < 32; kt++) {
        if (kt < 30) { CPA_WAIT2(); } else { CPA_WAIT0(); }
        __syncthreads();
        if (kt + 3 < 32) issue(kt + 3);

        uint32_t Ab = sb + SM_STAGE0 + (kt & 3) * STAGE_B;
        uint32_t Bbuf = Ab + 16384;
        uint32_t aBase = Ab + aOff;
        uint32_t bBase = Bbuf + bOff;

        #pragma unroll
        for (int ks = 0; ks < 4; ks++) {
            uint32_t a[2][4], b[2][4];
            uint32_t ca = (uint32_t)(((2 * ks + caH) ^ rin) * 16);
            uint32_t cb = (uint32_t)(((2 * ks + cbH) ^ rin) * 16);
            LDMX4(a[0], aBase + ca);
            LDMX4(a[1], aBase + 2048 + ca);
            LDMX4(b[0], bBase + cb);
            LDMX4(b[1], bBase + 2048 + cb);
            #pragma unroll
            for (int mi = 0; mi < 2; mi++)
                #pragma unroll
                for (int j = 0; j < 2; j++) {
                    MMA8(acc[mi][2*j],     a[mi], b[j][0], b[j][1]);
                    MMA8(acc[mi][2*j + 1], a[mi], b[j][2], b[j][3]);
                }
        }
    }

    // fused epilogue: (acc + b2) * routing weight -> g_comb
    int nv = min(128, cnt - mtile * 128);
    int q = lane & 3, rr = lane >> 2;
    const float* b2p = b2 + (size_t)e * H_ + ntile * 128 + wn * 32;
    int ocol0 = ntile * 128 + wn * 32;
    int slotbase = off + mtile * 128;
    #pragma unroll
    for (int mi = 0; mi < 2; mi++) {
        int r1 = wm * 32 + mi * 16 + rr;
        float sw1 = (r1 < nv)     ? g_sw[slotbase + r1]     : 0.f;
        float sw2 = (r1 + 8 < nv) ? g_sw[slotbase + r1 + 8] : 0.f;
        #pragma unroll
        for (int ni = 0; ni < 4; ni++) {
            int c0 = ni * 8 + 2 * q;
            float be = __ldg(b2p + c0);
            float bo = __ldg(b2p + c0 + 1);
            if (r1 < nv) {
                float2 v = make_float2((acc[mi][ni][0] + be) * sw1,
                                       (acc[mi][ni][1] + bo) * sw1);
                *(float2*)&g_comb[(size_t)(slotbase + r1) * H_ + ocol0 + c0] = v;
            }
            if (r1 + 8 < nv) {
                float2 v = make_float2((acc[mi][ni][2] + be) * sw2,
                                       (acc[mi][ni][3] + bo) * sw2);
                *(float2*)&g_comb[(size_t)(slotbase + r1 + 8) * H_ + ocol0 + c0] = v;
            }
        }
    }
}

// ---------------- kernel 5: combine + residual ----------------
__global__ void k_combine(const float* __restrict__ x, float* __restrict__ out) {
    int t = blockIdx.x;
    int s0 = g_tslot[t * KK + 0];
    int s1 = g_tslot[t * KK + 1];
    int s2 = g_tslot[t * KK + 2];
    int s3 = g_tslot[t * KK + 3];
    for (int h = threadIdx.x; h < H_; h += 256) {
        out[(size_t)t * H_ + h] = x[(size_t)t * H_ + h]
            + g_comb[(size_t)s0 * H_ + h]
            + g_comb[(size_t)s1 * H_ + h]
            + g_comb[(size_t)s2 * H_ + h]
            + g_comb[(size_t)s3 * H_ + h];
    }
}

// ---------------- launch ----------------
extern "C" void kernel_launch(void* const* d_in, const int* in_sizes, int n_in,
                              void* d_out, int out_size) {
    const float* x  = (const float*)d_in[0];
    const float* ns = (const float*)d_in[1];
    const float* gw = (const float*)d_in[2];
    const float* gb = (const float*)d_in[3];
    const float* w1 = (const float*)d_in[4];
    const float* b1 = (const float*)d_in[5];
    const float* w2 = (const float*)d_in[6];
    const float* b2 = (const float*)d_in[7];
    float* out = (float*)d_out;

    cudaFuncSetAttribute(k_mlp1, cudaFuncAttributeMaxDynamicSharedMemorySize, SMEM_MLP);
    cudaFuncSetAttribute(k_mlp2, cudaFuncAttributeMaxDynamicSharedMemorySize, SMEM_MLP);

    k_norm_gate<<<T_, 256>>>(x, ns, gw, gb);
    k_build<<<1, 1024>>>();
    k_mlp1<<<dim3(16, 8, 32), 512, SMEM_MLP>>>(w1, b1);
    k_mlp2<<<dim3(8, 8, 32), 512, SMEM_MLP>>>(w2, b2);
    k_combine<<<T_, 256>>>(x, out);
}

// round 10
// speedup vs baseline: 1.2016x; 1.2016x over previous
#include <cuda_runtime.h>
#include <cstdint>

#define E_    32
#define KK    4
#define H_    1024
#define F_    1024
#define T_    1024
#define TWO_F 2048
#define NSLOT (T_*KK)

// ---------------- scratch (device globals; no allocation) ----------------
__device__ float g_t[T_*H_];
__device__ float g_topk_w[T_*KK];
__device__ int   g_topk_i[T_*KK];
__device__ int   g_cnt[E_];
__device__ int   g_off[E_];
__device__ int   g_tok[NSLOT];
__device__ float g_sw[NSLOT];
__device__ int   g_tslot[T_*KK];
__device__ float g_act[(size_t)NSLOT*F_];
__device__ float g_comb[(size_t)NSLOT*H_];

// ---------------- helpers ----------------
__device__ __forceinline__ uint32_t smem_u32(const void* p) {
    uint32_t a;
    asm("{ .reg .u64 t; cvta.to.shared.u64 t, %1; cvt.u32.u64 %0, t; }" : "=r"(a) : "l"(p));
    return a;
}

#define CPA16(dst, src, sz) \
    asm volatile("cp.async.ca.shared.global [%0], [%1], 16, %2;" \
        :: "r"(dst), "l"(src), "r"(sz))

#define CPA_COMMIT() asm volatile("cp.async.commit_group;")
#define CPA_WAIT1()  asm volatile("cp.async.wait_group 1;")
#define CPA_WAIT0()  asm volatile("cp.async.wait_group 0;")

#define LDMX4(r, addr) \
    asm volatile("ldmatrix.sync.aligned.m8n8.x4.shared.b16 {%0,%1,%2,%3}, [%4];" \
        : "=r"((r)[0]), "=r"((r)[1]), "=r"((r)[2]), "=r"((r)[3]) : "r"(addr))

#define MMA8(d, a, b0, b1) \
    asm volatile("mma.sync.aligned.m16n8k8.row.col.f32.tf32.tf32.f32 " \
        "{%0,%1,%2,%3}, {%4,%5,%6,%7}, {%8,%9}, {%0,%1,%2,%3};" \
        : "+f"((d)[0]), "+f"((d)[1]), "+f"((d)[2]), "+f"((d)[3]) \
        : "r"((a)[0]), "r"((a)[1]), "r"((a)[2]), "r"((a)[3]), "r"(b0), "r"(b1))

// dynamic smem: [0,512) rowtok; stages at 1024: stage s -> A (16KB) + B (16KB)
#define SM_STAGE0  1024
#define STAGE_B    32768
#define SMEM_MLP   (SM_STAGE0 + 3 * STAGE_B)   // 99328 B -> 2 CTAs/SM

// ---------------- kernel 1: fused rmsnorm + gate + top-4 softmax ----------------
__global__ void __launch_bounds__(256) k_norm_gate(
    const float* __restrict__ x, const float* __restrict__ scale,
    const float* __restrict__ gw, const float* __restrict__ gb) {
    __shared__ float ts[H_];
    __shared__ float red[8];
    __shared__ float lg[E_];
    int t = blockIdx.x;
    const float* xr = x + (size_t)t * H_;
    float s = 0.f;
    float xv[4];
    #pragma unroll
    for (int i = 0; i < 4; i++) { xv[i] = xr[threadIdx.x + i * 256]; s += xv[i] * xv[i]; }
    for (int o = 16; o; o >>= 1) s += __shfl_down_sync(0xffffffffu, s, o);
    if ((threadIdx.x & 31) == 0) red[threadIdx.x >> 5] = s;
    __syncthreads();
    if (threadIdx.x < 8) {
        s = red[threadIdx.x];
        for (int o = 4; o; o >>= 1) s += __shfl_down_sync(0xffu, s, o);
        if (threadIdx.x == 0) red[0] = rsqrtf(s / (float)H_ + 1e-5f);
    }
    __syncthreads();
    float r = red[0];
    #pragma unroll
    for (int i = 0; i < 4; i++) {
        int h = threadIdx.x + i * 256;
        float v = xv[i] * r * scale[h];
        ts[h] = v;
        g_t[(size_t)t * H_ + h] = v;
    }
    __syncthreads();
    int e = threadIdx.x >> 3, j = threadIdx.x & 7;
    const float* wr = gw + (size_t)e * H_;
    float acc = 0.f;
    for (int h = j * 4; h < H_; h += 32)
        acc += ts[h]*wr[h] + ts[h+1]*wr[h+1] + ts[h+2]*wr[h+2] + ts[h+3]*wr[h+3];
    for (int o = 4; o; o >>= 1) acc += __shfl_down_sync(0xffffffffu, acc, o);
    if (j == 0) lg[e] = acc + gb[e];
    __syncthreads();
    if (threadIdx.x == 0) {
        float v[E_];
        #pragma unroll
        for (int i = 0; i < E_; i++) v[i] = lg[i];
        float tv[KK]; int ti[KK];
        for (int k = 0; k < KK; k++) {
            float best = -1e30f; int bi = 0;
            for (int i = 0; i < E_; i++) if (v[i] > best) { best = v[i]; bi = i; }
            tv[k] = best; ti[k] = bi; v[bi] = -1e30f;
        }
        float m = tv[0], den = 0.f, ex[KK];
        for (int k = 0; k < KK; k++) { ex[k] = expf(tv[k] - m); den += ex[k]; }
        for (int k = 0; k < KK; k++) {
            g_topk_w[t*KK + k] = ex[k] / den;
            g_topk_i[t*KK + k] = ti[k];
        }
    }
}

// ---------------- kernel 2: parallel deterministic grouping ----------------
__global__ void __launch_bounds__(1024) k_build() {
    __shared__ uint32_t wmask[32][E_];
    __shared__ int scanwe[32][E_];
    __shared__ int cnt_s[E_], off_s[E_];
    int t = threadIdx.x, w = t >> 5, lane = t & 31;

    ((uint32_t*)wmask)[t] = 0u;
    __syncthreads();

    int es[KK]; float ws[KK];
    #pragma unroll
    for (int j = 0; j < KK; j++) {
        es[j] = g_topk_i[t * KK + j];
        ws[j] = g_topk_w[t * KK + j];
        atomicOr(&wmask[w][es[j]], 1u << lane);
    }
    __syncthreads();

    if (t < E_) {
        int run = 0;
        #pragma unroll
        for (int ww = 0; ww < 32; ww++) {
            scanwe[ww][t] = run;
            run += __popc(wmask[ww][t]);
        }
        cnt_s[t] = run;
        g_cnt[t] = run;
    }
    __syncthreads();
    if (t == 0) {
        int r = 0;
        #pragma unroll
        for (int i = 0; i < E_; i++) { off_s[i] = r; g_off[i] = r; r += cnt_s[i]; }
    }
    __syncthreads();

    uint32_t ltmask = (1u << lane) - 1u;
    #pragma unroll
    for (int j = 0; j < KK; j++) {
        int e = es[j];
        int p = off_s[e] + scanwe[w][e] + __popc(wmask[w][e] & ltmask);
        g_tok[p] = t;
        g_sw[p] = ws[j];
        g_tslot[t * KK + j] = p;
    }
}

// =====================================================================
// grouped GEMM: BM=128, BN=128, BK=32, mma.sync m16n8k8 tf32,
// ldmatrix.x4.b16 on XOR-swizzled K-major tiles, 3-stage cp.async,
// 8 warps as 4(M)x2(N): warp tile 32x64, 2 CTAs/SM.
// Register-level fragment pipelining: A double-buffered, B rotated
// in place (reload b[j] right after its last MMA use in this ks).
// =====================================================================

__device__ __forceinline__ float swiglu(float glu, float lin) {
    glu = fminf(glu, 7.0f);
    lin = fminf(fmaxf(lin, -7.0f), 7.0f);
    float sig = 1.f / (1.f + __expf(-1.702f * glu));
    return glu * sig * (lin + 1.f);
}

__global__ void __launch_bounds__(256, 2)
k_mlp1(const float* __restrict__ w1, const float* __restrict__ b1) {
    extern __shared__ char smem[];
    int e = blockIdx.z, mtile = blockIdx.y, ntile = blockIdx.x;
    int cnt = g_cnt[e];
    if (mtile * 128 >= cnt) return;
    int off = g_off[e];
    int tid = threadIdx.x, wid = tid >> 5, lane = tid & 31;
    int wm = wid & 3, wn = wid >> 2;
    int grp = lane >> 3, rin = lane & 7;
    uint32_t sb = smem_u32(smem);

    int* rowtok = (int*)smem;
    if (tid < 128) {
        int m = mtile * 128 + tid;
        rowtok[tid] = (m < cnt) ? g_tok[off + m] : -1;
    }
    __syncthreads();

    const float* Bb = w1 + ((size_t)e * TWO_F + (size_t)ntile * 128) * H_;

    int frow = tid >> 3, fc = tid & 7;
    uint32_t fswz = (uint32_t)((fc ^ (frow & 7)) * 16);

    auto issue = [&](int kt) {
        int s = kt - (kt / 3) * 3;
        int k0 = kt * 32;
        uint32_t Ab = sb + SM_STAGE0 + s * STAGE_B;
        uint32_t Bbuf = Ab + 16384;
        #pragma unroll
        for (int i = 0; i < 4; i++) {
            int row = frow + i * 32;
            int tok = rowtok[row];
            const float* src = g_t + (size_t)(tok < 0 ? 0 : tok) * H_ + k0 + fc * 4;
            int sz = (tok >= 0) ? 16 : 0;
            CPA16(Ab + row * 128 + fswz, src, sz);
        }
        #pragma unroll
        for (int i = 0; i < 4; i++) {
            int row = frow + i * 32;
            const float* src = Bb + (size_t)row * H_ + k0 + fc * 4;
            CPA16(Bbuf + row * 128 + fswz, src, 16);
        }
        CPA_COMMIT();
    };

    float acc[2][8][4];
    #pragma unroll
    for (int mi = 0; mi < 2; mi++)
        #pragma unroll
        for (int ni = 0; ni < 8; ni++)
            #pragma unroll
            for (int q = 0; q < 4; q++) acc[mi][ni][q] = 0.f;

    issue(0); issue(1);

    uint32_t aOff = (uint32_t)((wm * 32 + (grp & 1) * 8 + rin) * 128);
    uint32_t bOff = (uint32_t)((wn * 64 + (grp >> 1) * 8 + rin) * 128);
    int caH = grp >> 1, cbH = grp & 1;

    for (int kt = 0; kt < 32; kt++) {
        int s = kt - (kt / 3) * 3;
        if (kt < 30) { CPA_WAIT1(); } else { CPA_WAIT0(); }
        __syncthreads();
        if (kt + 2 < 32) issue(kt + 2);

        uint32_t Ab = sb + SM_STAGE0 + s * STAGE_B;
        uint32_t Bbuf = Ab + 16384;
        uint32_t aBase = Ab + aOff;
        uint32_t bBase = Bbuf + bOff;

        uint32_t a[2][2][4], b[4][4];
        // prologue: fragments for ks=0
        {
            uint32_t ca = (uint32_t)((caH ^ rin) * 16);
            uint32_t cb = (uint32_t)((cbH ^ rin) * 16);
            LDMX4(a[0][0], aBase + ca);
            LDMX4(a[0][1], aBase + 2048 + ca);
            #pragma unroll
            for (int j = 0; j < 4; j++) LDMX4(b[j], bBase + j * 2048 + cb);
        }
        #pragma unroll
        for (int ks = 0; ks < 4; ks++) {
            int cur = ks & 1;
            uint32_t can = (uint32_t)(((2 * (ks + 1) + caH) ^ rin) * 16);
            uint32_t cbn = (uint32_t)(((2 * (ks + 1) + cbH) ^ rin) * 16);
            if (ks < 3) {                        // A double-buffer prefetch
                LDMX4(a[cur ^ 1][0], aBase + can);
                LDMX4(a[cur ^ 1][1], aBase + 2048 + can);
            }
            #pragma unroll
            for (int j = 0; j < 4; j++) {
                MMA8(acc[0][2*j],     a[cur][0], b[j][0], b[j][1]);
                MMA8(acc[1][2*j],     a[cur][1], b[j][0], b[j][1]);
                MMA8(acc[0][2*j + 1], a[cur][0], b[j][2], b[j][3]);
                MMA8(acc[1][2*j + 1], a[cur][1], b[j][2], b[j][3]);
                if (ks < 3) LDMX4(b[j], bBase + j * 2048 + cbn);   // rotate B in place
            }
        }
    }

    // fused epilogue: bias + interleaved swiglu, regs -> g_act
    int nv = min(128, cnt - mtile * 128);
    int q = lane & 3, rr = lane >> 2;
    const float* b1p = b1 + (size_t)e * TWO_F + ntile * 128 + wn * 64;
    int acol0 = ntile * 64 + wn * 32;
    int mrowbase = off + mtile * 128;
    #pragma unroll
    for (int mi = 0; mi < 2; mi++) {
        int r1 = wm * 32 + mi * 16 + rr;
        #pragma unroll
        for (int ni = 0; ni < 8; ni++) {
            float be = __ldg(b1p + ni * 8 + 2 * q);
            float bo = __ldg(b1p + ni * 8 + 2 * q + 1);
            int ac = acol0 + ni * 4 + q;
            if (r1 < nv)
                g_act[(size_t)(mrowbase + r1) * F_ + ac] =
                    swiglu(acc[mi][ni][0] + be, acc[mi][ni][1] + bo);
            if (r1 + 8 < nv)
                g_act[(size_t)(mrowbase + r1 + 8) * F_ + ac] =
                    swiglu(acc[mi][ni][2] + be, acc[mi][ni][3] + bo);
        }
    }
}

__global__ void __launch_bounds__(256, 2)
k_mlp2(const float* __restrict__ w2, const float* __restrict__ b2) {
    extern __shared__ char smem[];
    int e = blockIdx.z, mtile = blockIdx.y, ntile = blockIdx.x;
    int cnt = g_cnt[e];
    if (mtile * 128 >= cnt) return;
    int off = g_off[e];
    int tid = threadIdx.x, wid = tid >> 5, lane = tid & 31;
    int wm = wid & 3, wn = wid >> 2;
    int grp = lane >> 3, rin = lane & 7;
    uint32_t sb = smem_u32(smem);

    const float* Bb = w2 + ((size_t)e * H_ + (size_t)ntile * 128) * F_;

    int frow = tid >> 3, fc = tid & 7;
    uint32_t fswz = (uint32_t)((fc ^ (frow & 7)) * 16);

    auto issue = [&](int kt) {
        int s = kt - (kt / 3) * 3;
        int k0 = kt * 32;
        uint32_t Ab = sb + SM_STAGE0 + s * STAGE_B;
        uint32_t Bbuf = Ab + 16384;
        #pragma unroll
        for (int i = 0; i < 4; i++) {
            int row = frow + i * 32;
            int m = mtile * 128 + row;
            int mc = min(m, cnt - 1);
            const float* src = g_act + (size_t)(off + mc) * F_ + k0 + fc * 4;
            int sz = (m < cnt) ? 16 : 0;
            CPA16(Ab + row * 128 + fswz, src, sz);
        }
        #pragma unroll
        for (int i = 0; i < 4; i++) {
            int row = frow + i * 32;
            const float* src = Bb + (size_t)row * F_ + k0 + fc * 4;
            CPA16(Bbuf + row * 128 + fswz, src, 16);
        }
        CPA_COMMIT();
    };

    float acc[2][8][4];
    #pragma unroll
    for (int mi = 0; mi < 2; mi++)
        #pragma unroll
        for (int ni = 0; ni < 8; ni++)
            #pragma unroll
            for (int q = 0; q < 4; q++) acc[mi][ni][q] = 0.f;

    issue(0); issue(1);

    uint32_t aOff = (uint32_t)((wm * 32 + (grp & 1) * 8 + rin) * 128);
    uint32_t bOff = (uint32_t)((wn * 64 + (grp >> 1) * 8 + rin) * 128);
    int caH = grp >> 1, cbH = grp & 1;

    for (int kt = 0; kt < 32; kt++) {
        int s = kt - (kt / 3) * 3;
        if (kt < 30) { CPA_WAIT1(); } else { CPA_WAIT0(); }
        __syncthreads();
        if (kt + 2 < 32) issue(kt + 2);

        uint32_t Ab = sb + SM_STAGE0 + s * STAGE_B;
        uint32_t Bbuf = Ab + 16384;
        uint32_t aBase = Ab + aOff;
        uint32_t bBase = Bbuf + bOff;

        uint32_t a[2][2][4], b[4][4];
        {
            uint32_t ca = (uint32_t)((caH ^ rin) * 16);
            uint32_t cb = (uint32_t)((cbH ^ rin) * 16);
            LDMX4(a[0][0], aBase + ca);
            LDMX4(a[0][1], aBase + 2048 + ca);
            #pragma unroll
            for (int j = 0; j < 4; j++) LDMX4(b[j], bBase + j * 2048 + cb);
        }
        #pragma unroll
        for (int ks = 0; ks < 4; ks++) {
            int cur = ks & 1;
            uint32_t can = (uint32_t)(((2 * (ks + 1) + caH) ^ rin) * 16);
            uint32_t cbn = (uint32_t)(((2 * (ks + 1) + cbH) ^ rin) * 16);
            if (ks < 3) {
                LDMX4(a[cur ^ 1][0], aBase + can);
                LDMX4(a[cur ^ 1][1], aBase + 2048 + can);
            }
            #pragma unroll
            for (int j = 0; j < 4; j++) {
                MMA8(acc[0][2*j],     a[cur][0], b[j][0], b[j][1]);
                MMA8(acc[1][2*j],     a[cur][1], b[j][0], b[j][1]);
                MMA8(acc[0][2*j + 1], a[cur][0], b[j][2], b[j][3]);
                MMA8(acc[1][2*j + 1], a[cur][1], b[j][2], b[j][3]);
                if (ks < 3) LDMX4(b[j], bBase + j * 2048 + cbn);
            }
        }
    }

    // fused epilogue: (acc + b2) * routing weight -> g_comb
    int nv = min(128, cnt - mtile * 128);
    int q = lane & 3, rr = lane >> 2;
    const float* b2p = b2 + (size_t)e * H_ + ntile * 128 + wn * 64;
    int ocol0 = ntile * 128 + wn * 64;
    int slotbase = off + mtile * 128;
    #pragma unroll
    for (int mi = 0; mi < 2; mi++) {
        int r1 = wm * 32 + mi * 16 + rr;
        float sw1 = (r1 < nv)     ? g_sw[slotbase + r1]     : 0.f;
        float sw2 = (r1 + 8 < nv) ? g_sw[slotbase + r1 + 8] : 0.f;
        #pragma unroll
        for (int ni = 0; ni < 8; ni++) {
            int c0 = ni * 8 + 2 * q;
            float be = __ldg(b2p + c0);
            float bo = __ldg(b2p + c0 + 1);
            if (r1 < nv) {
                float2 v = make_float2((acc[mi][ni][0] + be) * sw1,
                                       (acc[mi][ni][1] + bo) * sw1);
                *(float2*)&g_comb[(size_t)(slotbase + r1) * H_ + ocol0 + c0] = v;
            }
            if (r1 + 8 < nv) {
                float2 v = make_float2((acc[mi][ni][2] + be) * sw2,
                                       (acc[mi][ni][3] + bo) * sw2);
                *(float2*)&g_comb[(size_t)(slotbase + r1 + 8) * H_ + ocol0 + c0] = v;
            }
        }
    }
}

// ---------------- kernel 5: combine + residual ----------------
__global__ void k_combine(const float* __restrict__ x, float* __restrict__ out) {
    int t = blockIdx.x;
    int s0 = g_tslot[t * KK + 0];
    int s1 = g_tslot[t * KK + 1];
    int s2 = g_tslot[t * KK + 2];
    int s3 = g_tslot[t * KK + 3];
    for (int h = threadIdx.x; h < H_; h += 256) {
        out[(size_t)t * H_ + h] = x[(size_t)t * H_ + h]
            + g_comb[(size_t)s0 * H_ + h]
            + g_comb[(size_t)s1 * H_ + h]
            + g_comb[(size_t)s2 * H_ + h]
            + g_comb[(size_t)s3 * H_ + h];
    }
}

// ---------------- launch ----------------
extern "C" void kernel_launch(void* const* d_in, const int* in_sizes, int n_in,
                              void* d_out, int out_size) {
    const float* x  = (const float*)d_in[0];
    const float* ns = (const float*)d_in[1];
    const float* gw = (const float*)d_in[2];
    const float* gb = (const float*)d_in[3];
    const float* w1 = (const float*)d_in[4];
    const float* b1 = (const float*)d_in[5];
    const float* w2 = (const float*)d_in[6];
    const float* b2 = (const float*)d_in[7];
    float* out = (float*)d_out;

    cudaFuncSetAttribute(k_mlp1, cudaFuncAttributeMaxDynamicSharedMemorySize, SMEM_MLP);
    cudaFuncSetAttribute(k_mlp2, cudaFuncAttributeMaxDynamicSharedMemorySize, SMEM_MLP);

    k_norm_gate<<<T_, 256>>>(x, ns, gw, gb);
    k_build<<<1, 1024>>>();
    k_mlp1<<<dim3(16, 8, 32), 256, SMEM_MLP>>>(w1, b1);
    k_mlp2<<<dim3(8, 8, 32), 256, SMEM_MLP>>>(w2, b2);
    k_combine<<<T_, 256>>>(x, out);
}